// round 1
// baseline (speedup 1.0000x reference)
#include <cuda_runtime.h>
#include <cstdint>

// Problem constants
#define BATCH 4
#define DIM   512
#define HEADS 8
#define DHEAD 64
#define HW    4096   // 64*64 query positions
#define LKV   1024   // 32*32 kv positions
#define KVK   2048   // im2col K for the 2x2 stride-2 conv (512*4)

// Scratch (device globals; allocation-free per harness rules)
__device__ float g_q [BATCH * DIM * HW];        // Q  [b][hd][s]   32 MB
__device__ float g_kv[BATCH * 2 * DIM * LKV];   // KV [b][o][ij]   16 MB
__device__ float g_o [BATCH * DIM * HW];        // attn out        32 MB

// ---------------------------------------------------------------------------
// Classic 128x128x8 tiled SGEMM:  C[b] = A @ B[b]
// A: [M,K] row-major (weights, shared across batch)
// B: [K,N] row-major, batched with stride K*N
// C: [M,N] row-major, batched with stride M*N
// 256 threads, 8x8 micro-tile per thread. M,N multiples of 128; K of 8.
// ---------------------------------------------------------------------------
template <int M, int N, int K>
__global__ __launch_bounds__(256)
void sgemm_kernel(const float* __restrict__ A,
                  const float* __restrict__ Bsrc,
                  float* __restrict__ Csrc)
{
    const int b = blockIdx.z;
    const float* Bp = Bsrc + (size_t)b * K * N;
    float*       Cp = Csrc + (size_t)b * M * N;

    __shared__ float As[8][128];
    __shared__ float Bs[8][128];

    const int tid  = threadIdx.x;
    const int tx   = tid & 15;
    const int ty   = tid >> 4;
    const int row0 = blockIdx.y * 128;
    const int col0 = blockIdx.x * 128;

    const int a_row = tid >> 1;          // 0..127
    const int a_col = (tid & 1) * 4;     // 0 or 4
    const int b_row = tid >> 5;          // 0..7
    const int b_col = (tid & 31) * 4;    // 0..124

    float acc[8][8];
#pragma unroll
    for (int i = 0; i < 8; i++)
#pragma unroll
        for (int j = 0; j < 8; j++) acc[i][j] = 0.f;

    for (int k0 = 0; k0 < K; k0 += 8) {
        float4 av = *reinterpret_cast<const float4*>(
            A + (size_t)(row0 + a_row) * K + k0 + a_col);
        As[a_col + 0][a_row] = av.x;
        As[a_col + 1][a_row] = av.y;
        As[a_col + 2][a_row] = av.z;
        As[a_col + 3][a_row] = av.w;
        *reinterpret_cast<float4*>(&Bs[b_row][b_col]) =
            *reinterpret_cast<const float4*>(
                Bp + (size_t)(k0 + b_row) * N + col0 + b_col);
        __syncthreads();

#pragma unroll
        for (int kk = 0; kk < 8; kk++) {
            float4 a0 = *reinterpret_cast<const float4*>(&As[kk][ty * 8]);
            float4 a1 = *reinterpret_cast<const float4*>(&As[kk][ty * 8 + 4]);
            float4 b0 = *reinterpret_cast<const float4*>(&Bs[kk][tx * 8]);
            float4 b1 = *reinterpret_cast<const float4*>(&Bs[kk][tx * 8 + 4]);
            float ar[8] = {a0.x, a0.y, a0.z, a0.w, a1.x, a1.y, a1.z, a1.w};
            float br[8] = {b0.x, b0.y, b0.z, b0.w, b1.x, b1.y, b1.z, b1.w};
#pragma unroll
            for (int i = 0; i < 8; i++)
#pragma unroll
                for (int j = 0; j < 8; j++)
                    acc[i][j] += ar[i] * br[j];
        }
        __syncthreads();
    }

#pragma unroll
    for (int i = 0; i < 8; i++) {
        float* crow = Cp + (size_t)(row0 + ty * 8 + i) * N + col0 + tx * 8;
        *reinterpret_cast<float4*>(crow)     = make_float4(acc[i][0], acc[i][1], acc[i][2], acc[i][3]);
        *reinterpret_cast<float4*>(crow + 4) = make_float4(acc[i][4], acc[i][5], acc[i][6], acc[i][7]);
    }
}

// ---------------------------------------------------------------------------
// KV conv as implicit-im2col GEMM.
// A = wkv flattened [1024][2048], k index = c*4 + p*2 + q (matches OIHW flat).
// B[k][n] = x[b][c][(2i+p)*64 + (2j+q)], n = i*32 + j.
// C = g_kv[b][o][n], M=1024, N=1024, K=2048.
// ---------------------------------------------------------------------------
__global__ __launch_bounds__(256)
void kv_gemm_kernel(const float* __restrict__ Wkv,
                    const float* __restrict__ X,
                    float* __restrict__ KVout)
{
    constexpr int M = 1024, N = 1024, K = 2048;
    const int b = blockIdx.z;
    const float* Xb = X + (size_t)b * DIM * HW;
    float*       Cp = KVout + (size_t)b * M * N;

    __shared__ float As[8][128];
    __shared__ float Bs[8][128];

    const int tid  = threadIdx.x;
    const int tx   = tid & 15;
    const int ty   = tid >> 4;
    const int row0 = blockIdx.y * 128;
    const int col0 = blockIdx.x * 128;

    const int a_row = tid >> 1;
    const int a_col = (tid & 1) * 4;
    const int b_row = tid >> 5;
    const int b_col = (tid & 31) * 4;

    float acc[8][8];
#pragma unroll
    for (int i = 0; i < 8; i++)
#pragma unroll
        for (int j = 0; j < 8; j++) acc[i][j] = 0.f;

    for (int k0 = 0; k0 < K; k0 += 8) {
        float4 av = *reinterpret_cast<const float4*>(
            Wkv + (size_t)(row0 + a_row) * K + k0 + a_col);
        As[a_col + 0][a_row] = av.x;
        As[a_col + 1][a_row] = av.y;
        As[a_col + 2][a_row] = av.z;
        As[a_col + 3][a_row] = av.w;

        {
            const int krow = k0 + b_row;         // 0..2047
            const int c  = krow >> 2;
            const int p  = (krow >> 1) & 1;
            const int qq = krow & 1;
            const float* xr = Xb + (size_t)c * HW + p * 64 + qq;
#pragma unroll
            for (int u = 0; u < 4; u++) {
                const int n  = col0 + b_col + u; // 0..1023
                const int ii = n >> 5;
                const int jj = n & 31;
                Bs[b_row][b_col + u] = xr[ii * 128 + jj * 2];
            }
        }
        __syncthreads();

#pragma unroll
        for (int kk = 0; kk < 8; kk++) {
            float4 a0 = *reinterpret_cast<const float4*>(&As[kk][ty * 8]);
            float4 a1 = *reinterpret_cast<const float4*>(&As[kk][ty * 8 + 4]);
            float4 b0 = *reinterpret_cast<const float4*>(&Bs[kk][tx * 8]);
            float4 b1 = *reinterpret_cast<const float4*>(&Bs[kk][tx * 8 + 4]);
            float ar[8] = {a0.x, a0.y, a0.z, a0.w, a1.x, a1.y, a1.z, a1.w};
            float br[8] = {b0.x, b0.y, b0.z, b0.w, b1.x, b1.y, b1.z, b1.w};
#pragma unroll
            for (int i = 0; i < 8; i++)
#pragma unroll
                for (int j = 0; j < 8; j++)
                    acc[i][j] += ar[i] * br[j];
        }
        __syncthreads();
    }

#pragma unroll
    for (int i = 0; i < 8; i++) {
        float* crow = Cp + (size_t)(row0 + ty * 8 + i) * N + col0 + tx * 8;
        *reinterpret_cast<float4*>(crow)     = make_float4(acc[i][0], acc[i][1], acc[i][2], acc[i][3]);
        *reinterpret_cast<float4*>(crow + 4) = make_float4(acc[i][4], acc[i][5], acc[i][6], acc[i][7]);
    }
}

// ---------------------------------------------------------------------------
// Fused flash-style attention, fp32.
// Grid: (HW/64, HEADS, BATCH), 64 threads per CTA, one thread = one query row.
// Q stored [b][hd][s] -> per-thread q[64] in registers (coalesced loads).
// K/V tiles (64 cols) staged in padded smem; online softmax with 16-wide
// score sub-chunks to keep register count bounded (q[64]+O[64]+s[16]).
// ---------------------------------------------------------------------------
__global__ __launch_bounds__(64)
void attn_kernel(const float* __restrict__ Q,
                 const float* __restrict__ KV,
                 float* __restrict__ Oout)
{
    const int bb = blockIdx.z;
    const int h  = blockIdx.y;
    const int i0 = blockIdx.x * 64;
    const int t  = threadIdx.x;

    const float* Qb = Q  + ((size_t)bb * DIM + h * DHEAD) * HW;
    const float* Kb = KV + ((size_t)bb * 2 * DIM + h * DHEAD) * LKV;
    const float* Vb = KV + ((size_t)bb * 2 * DIM + DIM + h * DHEAD) * LKV;
    float*       Ob = Oout + ((size_t)bb * DIM + h * DHEAD) * HW;

    __shared__ float Ks[64][65];
    __shared__ float Vs[64][65];

    float q[64], O[64];
#pragma unroll
    for (int dd = 0; dd < 64; dd++) {
        q[dd] = Qb[(size_t)dd * HW + i0 + t] * 0.125f;   // fold scale=d^-0.5
        O[dd] = 0.f;
    }

    float m = -1e30f, l = 0.f;

    for (int j0 = 0; j0 < LKV; j0 += 64) {
        __syncthreads();
#pragma unroll
        for (int dd = 0; dd < 64; dd++) {
            Ks[dd][t] = Kb[(size_t)dd * LKV + j0 + t];
            Vs[dd][t] = Vb[(size_t)dd * LKV + j0 + t];
        }
        __syncthreads();

#pragma unroll
        for (int sub = 0; sub < 4; sub++) {
            float s[16];
            float smax = -1e30f;
#pragma unroll
            for (int jj = 0; jj < 16; jj++) {
                float acc = 0.f;
#pragma unroll
                for (int dd = 0; dd < 64; dd++)
                    acc += q[dd] * Ks[dd][sub * 16 + jj];
                s[jj] = acc;
                smax  = fmaxf(smax, acc);
            }
            if (smax > m) {
                const float f = __expf(m - smax);
                m = smax;
                l *= f;
#pragma unroll
                for (int dd = 0; dd < 64; dd++) O[dd] *= f;
            }
#pragma unroll
            for (int jj = 0; jj < 16; jj++) {
                const float p = __expf(s[jj] - m);
                l += p;
#pragma unroll
                for (int dd = 0; dd < 64; dd++)
                    O[dd] += p * Vs[dd][sub * 16 + jj];
            }
        }
    }

    const float inv = 1.f / l;
#pragma unroll
    for (int dd = 0; dd < 64; dd++)
        Ob[(size_t)dd * HW + i0 + t] = O[dd] * inv;
}

// ---------------------------------------------------------------------------
// Launch
// ---------------------------------------------------------------------------
extern "C" void kernel_launch(void* const* d_in, const int* in_sizes, int n_in,
                              void* d_out, int out_size)
{
    const float* x    = (const float*)d_in[0];   // [4,512,64,64]
    const float* wq   = (const float*)d_in[1];   // [512,512,1,1]
    const float* wkv  = (const float*)d_in[2];   // [1024,512,2,2]
    const float* wout = (const float*)d_in[3];   // [512,512,1,1]
    float* out = (float*)d_out;                  // [4,512,64,64]

    float *qbuf, *kvbuf, *obuf;
    cudaGetSymbolAddress((void**)&qbuf,  g_q);
    cudaGetSymbolAddress((void**)&kvbuf, g_kv);
    cudaGetSymbolAddress((void**)&obuf,  g_o);

    // Q = Wq @ X   : M=512, N=4096, K=512, batched over 4
    sgemm_kernel<512, 4096, 512><<<dim3(32, 4, BATCH), 256>>>(wq, x, qbuf);

    // KV = Wkv @ im2col(X) : M=1024, N=1024, K=2048
    kv_gemm_kernel<<<dim3(8, 8, BATCH), 256>>>(wkv, x, kvbuf);

    // Fused attention
    attn_kernel<<<dim3(HW / 64, HEADS, BATCH), 64>>>(qbuf, kvbuf, obuf);

    // Y = Wout @ O
    sgemm_kernel<512, 4096, 512><<<dim3(32, 4, BATCH), 256>>>(wout, obuf, out);
}